// round 1
// baseline (speedup 1.0000x reference)
#include <cuda_runtime.h>
#include <cuda_bf16.h>
#include <cstdint>
#include <cfloat>

#define N_EMB 12544
#define M_MB  16384
#define D_DIM 1536
#define B_SZ  16
#define P_PT  (N_EMB / B_SZ)     // 784
#define NCB   (M_MB / 128)       // 128 column blocks
#define NRB   (N_EMB / 128)      // 98 row blocks
#define KTILES (D_DIM / 32)      // 48

// ---------------- device scratch (static: no allocations allowed) ----------------
__device__ __nv_bfloat16 g_embB[(size_t)N_EMB * D_DIM];   // 38.5 MB
__device__ __nv_bfloat16 g_mbB[(size_t)M_MB * D_DIM];     // 50.3 MB
__device__ float g_x2[N_EMB];
__device__ float g_y2[M_MB];
struct __align__(16) Top2 { float v0, v1; int i0, i1; };
__device__ Top2 g_top2[(size_t)N_EMB * NCB];              // 25.7 MB
__device__ float g_pscore[N_EMB];
__device__ int   g_ploc[N_EMB];
__device__ float g_bscore[B_SZ];
__device__ int   g_bn[B_SZ];
__device__ int   g_bnn[B_SZ];
__device__ float g_d2b[(size_t)B_SZ * M_MB];              // 1 MB

// ---------------- K1: fp32 -> bf16 conversion + row squared norms ----------------
__global__ void prep_kernel(const float* __restrict__ src, int which) {
    const int row = blockIdx.x;
    const float4* s = reinterpret_cast<const float4*>(src) + (size_t)row * (D_DIM / 4);
    __nv_bfloat162* d = reinterpret_cast<__nv_bfloat162*>(which ? g_mbB : g_embB)
                        + (size_t)row * (D_DIM / 2);
    float acc = 0.f;
    for (int i = threadIdx.x; i < D_DIM / 4; i += blockDim.x) {
        float4 v = s[i];
        acc += v.x * v.x + v.y * v.y + v.z * v.z + v.w * v.w;
        d[2 * i]     = __floats2bfloat162_rn(v.x, v.y);
        d[2 * i + 1] = __floats2bfloat162_rn(v.z, v.w);
    }
#pragma unroll
    for (int off = 16; off; off >>= 1) acc += __shfl_xor_sync(0xffffffffu, acc, off);
    __shared__ float ws[4];
    if ((threadIdx.x & 31) == 0) ws[threadIdx.x >> 5] = acc;
    __syncthreads();
    if (threadIdx.x == 0) {
        float t = ws[0] + ws[1] + ws[2] + ws[3];
        if (which) g_y2[row] = t; else g_x2[row] = t;
    }
}

// ---------------- K2: fused bf16 GEMM (S = X*Y^T) + per-(row, colblock) top-2 ----------------
__device__ __forceinline__ void mma_bf16(float* c, const uint32_t* a, uint32_t b0, uint32_t b1) {
    asm volatile(
        "mma.sync.aligned.m16n8k16.row.col.f32.bf16.bf16.f32 "
        "{%0,%1,%2,%3}, {%4,%5,%6,%7}, {%8,%9}, {%0,%1,%2,%3};\n"
        : "+f"(c[0]), "+f"(c[1]), "+f"(c[2]), "+f"(c[3])
        : "r"(a[0]), "r"(a[1]), "r"(a[2]), "r"(a[3]), "r"(b0), "r"(b1));
}

__global__ void __launch_bounds__(256)
gemm_min_kernel() {
    const int m0 = blockIdx.x * 128;   // memory-bank columns
    const int n0 = blockIdx.y * 128;   // embedding rows
    const int tid  = threadIdx.x;
    const int lane = tid & 31;
    const int warp = tid >> 5;
    const int warpM = warp & 3;        // 4 row-warps (32 rows each)
    const int warpN = warp >> 2;       // 2 col-warps (64 cols each)

    // union: GEMM double buffers (40960B)  /  epilogue epi[128][65] + y2s[128] (33792B)
    __shared__ __align__(16) unsigned char smraw[40960];
    __nv_bfloat16* smA = reinterpret_cast<__nv_bfloat16*>(smraw);            // [2][128][40]
    __nv_bfloat16* smB = reinterpret_cast<__nv_bfloat16*>(smraw + 20480);    // [2][128][40]

    float acc[2][8][4];
#pragma unroll
    for (int mi = 0; mi < 2; ++mi)
#pragma unroll
        for (int ni = 0; ni < 8; ++ni)
#pragma unroll
            for (int q = 0; q < 4; ++q) acc[mi][ni][q] = 0.f;

    const int lr = tid >> 2;          // 0..63
    const int lc = (tid & 3) * 8;     // 0,8,16,24
    const __nv_bfloat16* gA = g_embB + (size_t)(n0 + lr) * D_DIM + lc;
    const __nv_bfloat16* gB = g_mbB  + (size_t)(m0 + lr) * D_DIM + lc;

    uint4 ra0, ra1, rb0, rb1;
    ra0 = *(const uint4*)(gA);
    ra1 = *(const uint4*)(gA + (size_t)64 * D_DIM);
    rb0 = *(const uint4*)(gB);
    rb1 = *(const uint4*)(gB + (size_t)64 * D_DIM);
    *(uint4*)&smA[(size_t)(lr) * 40 + lc]        = ra0;
    *(uint4*)&smA[(size_t)(lr + 64) * 40 + lc]   = ra1;
    *(uint4*)&smB[(size_t)(lr) * 40 + lc]        = rb0;
    *(uint4*)&smB[(size_t)(lr + 64) * 40 + lc]   = rb1;
    __syncthreads();

    const int fr = lane >> 2;         // fragment row within 8
    const int fc = (lane & 3) * 2;    // fragment k within 8

    for (int t = 0; t < KTILES; ++t) {
        if (t + 1 < KTILES) {
            const int k0 = (t + 1) * 32;
            ra0 = *(const uint4*)(gA + k0);
            ra1 = *(const uint4*)(gA + (size_t)64 * D_DIM + k0);
            rb0 = *(const uint4*)(gB + k0);
            rb1 = *(const uint4*)(gB + (size_t)64 * D_DIM + k0);
        }
        const int buf = t & 1;
        const __nv_bfloat16* At = smA + (size_t)buf * 128 * 40;
        const __nv_bfloat16* Bt = smB + (size_t)buf * 128 * 40;
#pragma unroll
        for (int ks = 0; ks < 32; ks += 16) {
            uint32_t af[2][4];
#pragma unroll
            for (int mi = 0; mi < 2; ++mi) {
                const __nv_bfloat16* ap = At + (warpM * 32 + mi * 16 + fr) * 40 + ks + fc;
                af[mi][0] = *(const uint32_t*)(ap);
                af[mi][1] = *(const uint32_t*)(ap + 8 * 40);
                af[mi][2] = *(const uint32_t*)(ap + 8);
                af[mi][3] = *(const uint32_t*)(ap + 8 * 40 + 8);
            }
#pragma unroll
            for (int ni = 0; ni < 8; ++ni) {
                const __nv_bfloat16* bp = Bt + (warpN * 64 + ni * 8 + fr) * 40 + ks + fc;
                uint32_t b0 = *(const uint32_t*)(bp);
                uint32_t b1 = *(const uint32_t*)(bp + 8);
                mma_bf16(acc[0][ni], af[0], b0, b1);
                mma_bf16(acc[1][ni], af[1], b0, b1);
            }
        }
        if (t + 1 < KTILES) {
            const int nb = buf ^ 1;
            // safe pre-sync: buffer nb was last READ in iteration t-1, which ended with a barrier
            *(uint4*)&smA[(size_t)(nb * 128 + lr) * 40 + lc]      = ra0;
            *(uint4*)&smA[(size_t)(nb * 128 + lr + 64) * 40 + lc] = ra1;
            *(uint4*)&smB[(size_t)(nb * 128 + lr) * 40 + lc]      = rb0;
            *(uint4*)&smB[(size_t)(nb * 128 + lr + 64) * 40 + lc] = rb1;
        }
        __syncthreads();
    }

    // ---- epilogue: d2approx = y2[m] - 2*S  (x2 is a per-row constant; added in refine) ----
    float* epi = reinterpret_cast<float*>(smraw);            // [128][65] (padded: no bank conflicts)
    float* y2s = reinterpret_cast<float*>(smraw + 33280);    // [128]
    if (tid < 128) y2s[tid] = g_y2[m0 + tid];

    float tv0 = FLT_MAX, tv1 = FLT_MAX;
    int   ti0 = 0, ti1 = 0;
#pragma unroll
    for (int h = 0; h < 2; ++h) {
        if (h) __syncthreads();        // h=0 is covered by the loop-final barrier above
        if (warpN == h) {
#pragma unroll
            for (int mi = 0; mi < 2; ++mi)
#pragma unroll
                for (int ni = 0; ni < 8; ++ni) {
                    const int row = warpM * 32 + mi * 16 + fr;
                    const int col = ni * 8 + fc;
                    epi[row * 65 + col]           = acc[mi][ni][0];
                    epi[row * 65 + col + 1]       = acc[mi][ni][1];
                    epi[(row + 8) * 65 + col]     = acc[mi][ni][2];
                    epi[(row + 8) * 65 + col + 1] = acc[mi][ni][3];
                }
        }
        __syncthreads();
        if (tid < 128) {
#pragma unroll 1
            for (int j = 0; j < 64; ++j) {
                const float v = y2s[h * 64 + j] - 2.f * epi[tid * 65 + j];
                const int idx = m0 + h * 64 + j;
                if (v < tv0)      { tv1 = tv0; ti1 = ti0; tv0 = v; ti0 = idx; }
                else if (v < tv1) { tv1 = v; ti1 = idx; }
            }
        }
    }
    if (tid < 128) {
        Top2 t; t.v0 = tv0; t.v1 = tv1; t.i0 = ti0; t.i1 = ti1;
        g_top2[(size_t)(n0 + tid) * NCB + blockIdx.x] = t;
    }
}

// ---------------- K3: per-row candidate refinement in exact fp32 ----------------
__global__ void refine_kernel(const float* __restrict__ emb, const float* __restrict__ mb) {
    const int lane = threadIdx.x & 31;
    const int n = blockIdx.x * 8 + (threadIdx.x >> 5);

    float cv[8]; int ci[8];
    const Top2* tp = g_top2 + (size_t)n * NCB + lane * 4;
#pragma unroll
    for (int s = 0; s < 4; ++s) {
        Top2 t = tp[s];
        cv[2 * s]     = t.v0; ci[2 * s]     = t.i0;
        cv[2 * s + 1] = t.v1; ci[2 * s + 1] = t.i1;
    }
    // select the 8 globally-smallest approx candidates (out of 256)
    int sel[8];
#pragma unroll 1
    for (int r = 0; r < 8; ++r) {
        float bv = FLT_MAX; int bi = 0x7fffffff;
#pragma unroll
        for (int j = 0; j < 8; ++j)
            if (cv[j] < bv || (cv[j] == bv && ci[j] < bi)) { bv = cv[j]; bi = ci[j]; }
#pragma unroll
        for (int off = 16; off; off >>= 1) {
            float ov = __shfl_xor_sync(0xffffffffu, bv, off);
            int   oi = __shfl_xor_sync(0xffffffffu, bi, off);
            if (ov < bv || (ov == bv && oi < bi)) { bv = ov; bi = oi; }
        }
        sel[r] = bi;
#pragma unroll
        for (int j = 0; j < 8; ++j)
            if (ci[j] == bi) cv[j] = FLT_MAX;
    }
    // exact fp32 distances to the 8 candidates (same formula as reference: x2 + y2 - 2*dot)
    float4 xl[12];
    const float4* x4 = reinterpret_cast<const float4*>(emb) + (size_t)n * (D_DIM / 4);
#pragma unroll
    for (int j = 0; j < 12; ++j) xl[j] = x4[lane + j * 32];
    const float xn = g_x2[n];
    float bestd = FLT_MAX; int besti = 0x7fffffff;
#pragma unroll 1
    for (int r = 0; r < 8; ++r) {
        const int m = sel[r];
        const float4* y4 = reinterpret_cast<const float4*>(mb) + (size_t)m * (D_DIM / 4);
        float s = 0.f;
#pragma unroll
        for (int j = 0; j < 12; ++j) {
            float4 bv = y4[lane + j * 32];
            s += xl[j].x * bv.x + xl[j].y * bv.y + xl[j].z * bv.z + xl[j].w * bv.w;
        }
#pragma unroll
        for (int off = 16; off; off >>= 1) s += __shfl_xor_sync(0xffffffffu, s, off);
        const float d2 = xn + g_y2[m] - 2.f * s;
        if (d2 < bestd || (d2 == bestd && m < besti)) { bestd = d2; besti = m; }
    }
    if (lane == 0) {
        g_pscore[n] = sqrtf(fmaxf(bestd, 0.f));
        g_ploc[n]   = besti;
    }
}

// ---------------- K4: per-batch argmax over patch scores ----------------
__global__ void argmax_kernel() {
    const int b = blockIdx.x;
    const int base = b * P_PT;
    const int tid = threadIdx.x;
    float bv = -FLT_MAX; int bi = 0x7fffffff;
    for (int i = tid; i < P_PT; i += 256) {
        const float v = g_pscore[base + i];
        if (v > bv || (v == bv && i < bi)) { bv = v; bi = i; }
    }
    __shared__ float sv[256]; __shared__ int si[256];
    sv[tid] = bv; si[tid] = bi;
    __syncthreads();
    for (int s = 128; s; s >>= 1) {
        if (tid < s) {
            if (sv[tid + s] > sv[tid] || (sv[tid + s] == sv[tid] && si[tid + s] < si[tid])) {
                sv[tid] = sv[tid + s]; si[tid] = si[tid + s];
            }
        }
        __syncthreads();
    }
    if (tid == 0) {
        const int n = base + si[0];
        g_bscore[b] = sv[0];
        g_bn[b]     = n;
        g_bnn[b]    = g_ploc[n];
    }
}

// ---------------- K5: fp32 distances nn_sample[b] <-> memory_bank ----------------
__global__ void stage2_kernel(const float* __restrict__ mb) {
    const int lane = threadIdx.x & 31;
    const int m = blockIdx.x * 8 + (threadIdx.x >> 5);
    const float4* y4 = reinterpret_cast<const float4*>(mb) + (size_t)m * (D_DIM / 4);
    float4 yl[12];
#pragma unroll
    for (int j = 0; j < 12; ++j) yl[j] = y4[lane + j * 32];
    const float ym = g_y2[m];
#pragma unroll 1
    for (int b = 0; b < B_SZ; ++b) {
        const int nn = g_bnn[b];
        const float4* x4 = reinterpret_cast<const float4*>(mb) + (size_t)nn * (D_DIM / 4);
        float s = 0.f;
#pragma unroll
        for (int j = 0; j < 12; ++j) {
            float4 a = x4[lane + j * 32];
            s += yl[j].x * a.x + yl[j].y * a.y + yl[j].z * a.z + yl[j].w * a.w;
        }
#pragma unroll
        for (int off = 16; off; off >>= 1) s += __shfl_xor_sync(0xffffffffu, s, off);
        if (lane == 0) g_d2b[(size_t)b * M_MB + m] = g_y2[nn] + ym - 2.f * s;
    }
}

// ---------------- K6: top-9 support, softmax re-weighting, output ----------------
__global__ void finalize_kernel(const float* __restrict__ emb, const float* __restrict__ mb,
                                float* __restrict__ out) {
    const int b = blockIdx.x;
    const int tid = threadIdx.x;
    __shared__ int sel[9];
    __shared__ float dist9[9];
    __shared__ float rv[256]; __shared__ int ri[256];
    const float* d2 = g_d2b + (size_t)b * M_MB;

    for (int j = 0; j < 9; ++j) {           // 9x iterative argmin = ascending order, low-idx ties
        float bv = FLT_MAX; int bi = 0x7fffffff;
        for (int m = tid; m < M_MB; m += 256) {
            bool used = false;
            for (int q = 0; q < j; ++q) used |= (sel[q] == m);
            const float v = d2[m];
            if (!used && (v < bv || (v == bv && m < bi))) { bv = v; bi = m; }
        }
        rv[tid] = bv; ri[tid] = bi;
        __syncthreads();
        for (int s = 128; s; s >>= 1) {
            if (tid < s) {
                if (rv[tid + s] < rv[tid] || (rv[tid + s] == rv[tid] && ri[tid + s] < ri[tid])) {
                    rv[tid] = rv[tid + s]; ri[tid] = ri[tid + s];
                }
            }
            __syncthreads();
        }
        if (tid == 0) sel[j] = ri[0];
        __syncthreads();
    }

    const float* xp = emb + (size_t)g_bn[b] * D_DIM;
    for (int j = 0; j < 9; ++j) {           // reference uses the diff-square form here
        const float* y = mb + (size_t)sel[j] * D_DIM;
        float s = 0.f;
        for (int k = tid; k < D_DIM; k += 256) { const float df = xp[k] - y[k]; s += df * df; }
        rv[tid] = s;
        __syncthreads();
        for (int st = 128; st; st >>= 1) {
            if (tid < st) rv[tid] += rv[tid + st];
            __syncthreads();
        }
        if (tid == 0) dist9[j] = sqrtf(fmaxf(rv[0], 0.f));
        __syncthreads();
    }
    if (tid == 0) {
        float mx = dist9[0];
        for (int j = 1; j < 9; ++j) mx = fmaxf(mx, dist9[j]);
        float sum = 0.f, e0 = 0.f;
        for (int j = 0; j < 9; ++j) {
            const float e = expf(dist9[j] - mx);
            if (j == 0) e0 = e;
            sum += e;
        }
        out[b] = (1.f - e0 / sum) * g_bscore[b];
    }
}

// ---------------- launch ----------------
extern "C" void kernel_launch(void* const* d_in, const int* in_sizes, int n_in,
                              void* d_out, int out_size) {
    const float* emb = (const float*)d_in[0];
    const float* mb  = (const float*)d_in[1];
    float* out = (float*)d_out;

    prep_kernel<<<N_EMB, 128>>>(emb, 0);
    prep_kernel<<<M_MB, 128>>>(mb, 1);
    gemm_min_kernel<<<dim3(NCB, NRB), 256>>>();
    refine_kernel<<<N_EMB / 8, 256>>>(emb, mb);
    argmax_kernel<<<B_SZ, 256>>>();
    stage2_kernel<<<M_MB / 8, 256>>>(mb);
    finalize_kernel<<<B_SZ, 256>>>(emb, mb, out);
}

// round 4
// speedup vs baseline: 1.3692x; 1.3692x over previous
#include <cuda_runtime.h>
#include <cuda_bf16.h>
#include <cstdint>
#include <cfloat>

#define N_EMB 12544
#define M_MB  16384
#define D_DIM 1536
#define B_SZ  16
#define P_PT  (N_EMB / B_SZ)     // 784
#define NCB   (M_MB / 128)       // 128 column blocks
#define KSTAGE 64
#define NKSTAGES (D_DIM / KSTAGE) // 24
#define NSTAGE 4
#define A_STG 32768               // 256 rows x 128B
#define B_STG 16384               // 128 rows x 128B
#define STG_BYTES (A_STG + B_STG) // 49152
#define GEMM_SMEM (NSTAGE * STG_BYTES)  // 196608

// ---------------- device scratch (static: no allocations allowed) ----------------
__device__ __nv_bfloat16 g_embB[(size_t)N_EMB * D_DIM];   // 38.5 MB
__device__ __nv_bfloat16 g_mbB[(size_t)M_MB * D_DIM];     // 50.3 MB
__device__ float g_x2[N_EMB];
__device__ float g_y2[M_MB];
struct __align__(16) Top2 { float v0, v1; int i0, i1; };
__device__ Top2 g_top2[(size_t)N_EMB * NCB];              // 25.7 MB
__device__ float g_pscore[N_EMB];
__device__ int   g_ploc[N_EMB];
__device__ float g_bscore[B_SZ];
__device__ int   g_bn[B_SZ];
__device__ int   g_bnn[B_SZ];
__device__ float g_d2b[(size_t)B_SZ * M_MB];              // 1 MB

// ---------------- helpers ----------------
__device__ __forceinline__ uint32_t smem_u32(const void* p) {
    uint32_t a;
    asm("{ .reg .u64 t; cvta.to.shared.u64 t, %1; cvt.u32.u64 %0, t; }" : "=r"(a) : "l"(p));
    return a;
}
__device__ __forceinline__ void cp_async16(uint32_t saddr, const void* gaddr) {
    asm volatile("cp.async.cg.shared.global [%0], [%1], 16;" :: "r"(saddr), "l"(gaddr) : "memory");
}
#define CP_COMMIT() asm volatile("cp.async.commit_group;" ::: "memory")
#define CP_WAIT2()  asm volatile("cp.async.wait_group 2;" ::: "memory")
#define CP_WAIT0()  asm volatile("cp.async.wait_group 0;" ::: "memory")
__device__ __forceinline__ void ldmx4(uint32_t* r, uint32_t addr) {
    asm volatile("ldmatrix.sync.aligned.m8n8.x4.shared.b16 {%0,%1,%2,%3}, [%4];"
                 : "=r"(r[0]), "=r"(r[1]), "=r"(r[2]), "=r"(r[3]) : "r"(addr));
}
__device__ __forceinline__ void mma_bf16(float* c, const uint32_t* a, uint32_t b0, uint32_t b1) {
    asm volatile(
        "mma.sync.aligned.m16n8k16.row.col.f32.bf16.bf16.f32 "
        "{%0,%1,%2,%3}, {%4,%5,%6,%7}, {%8,%9}, {%0,%1,%2,%3};\n"
        : "+f"(c[0]), "+f"(c[1]), "+f"(c[2]), "+f"(c[3])
        : "r"(a[0]), "r"(a[1]), "r"(a[2]), "r"(a[3]), "r"(b0), "r"(b1));
}
// swizzle: 128B rows, XOR 16B-chunk by row%8 (conflict-free ldmatrix + cp.async)
__device__ __forceinline__ uint32_t swz(uint32_t row, uint32_t kbyte) {
    return row * 128 + (kbyte ^ ((row & 7) << 4));
}

// ---------------- K1: fp32 -> bf16 conversion + row squared norms ----------------
__global__ void prep_kernel(const float* __restrict__ src, int which) {
    const int row = blockIdx.x;
    const float4* s = reinterpret_cast<const float4*>(src) + (size_t)row * (D_DIM / 4);
    __nv_bfloat162* d = reinterpret_cast<__nv_bfloat162*>(which ? g_mbB : g_embB)
                        + (size_t)row * (D_DIM / 2);
    float acc = 0.f;
    for (int i = threadIdx.x; i < D_DIM / 4; i += blockDim.x) {
        float4 v = s[i];
        acc += v.x * v.x + v.y * v.y + v.z * v.z + v.w * v.w;
        d[2 * i]     = __floats2bfloat162_rn(v.x, v.y);
        d[2 * i + 1] = __floats2bfloat162_rn(v.z, v.w);
    }
#pragma unroll
    for (int off = 16; off; off >>= 1) acc += __shfl_xor_sync(0xffffffffu, acc, off);
    __shared__ float ws[4];
    if ((threadIdx.x & 31) == 0) ws[threadIdx.x >> 5] = acc;
    __syncthreads();
    if (threadIdx.x == 0) {
        float t = ws[0] + ws[1] + ws[2] + ws[3];
        if (which) g_y2[row] = t; else g_x2[row] = t;
    }
}

// ---------------- K2: pipelined bf16 mma.sync GEMM 256n x 128m + top-2 epilogue ----------------
__global__ void __launch_bounds__(512, 1)
gemm_min_kernel() {
    extern __shared__ __align__(1024) unsigned char smem[];
    const uint32_t sb = smem_u32(smem);
    const int tid = threadIdx.x;
    const int lane = tid & 31;
    const int warp = tid >> 5;
    const int warpM = warp & 7;      // 8 row-warps  (32 emb rows each)
    const int warpN = warp >> 3;     // 2 col-warps  (64 mb cols each)
    const int m0 = blockIdx.x * 128; // memory-bank columns
    const int n0 = blockIdx.y * 256; // embedding rows

    float acc[2][8][4];
#pragma unroll
    for (int mi = 0; mi < 2; ++mi)
#pragma unroll
        for (int ni = 0; ni < 8; ++ni)
#pragma unroll
            for (int q = 0; q < 4; ++q) acc[mi][ni][q] = 0.f;

    // cp.async source/dest precompute: A 256 rows (4 per thread), B 128 rows (2 per thread)
    const int crow = tid >> 3;            // 0..63
    const int cchk = tid & 7;             // 16B chunk within 128B row
    const __nv_bfloat16* gA = g_embB + (size_t)(n0 + crow) * D_DIM + cchk * 8;
    const __nv_bfloat16* gB = g_mbB  + (size_t)(m0 + crow) * D_DIM + cchk * 8;
    uint32_t sAo[4], sBo[2];
#pragma unroll
    for (int i = 0; i < 4; ++i) sAo[i] = swz(crow + i * 64, cchk * 16);
#pragma unroll
    for (int i = 0; i < 2; ++i) sBo[i] = sAo[i] + A_STG;   // same row geometry, B region

#define LOAD_STAGE(s, t)                                                              \
    do {                                                                              \
        const uint32_t base = sb + (uint32_t)((s) % NSTAGE) * STG_BYTES;              \
        const size_t ke = (size_t)(t) * KSTAGE;                                       \
        _Pragma("unroll")                                                             \
        for (int i = 0; i < 4; ++i)                                                   \
            cp_async16(base + sAo[i], gA + (size_t)i * 64 * D_DIM + ke);              \
        _Pragma("unroll")                                                             \
        for (int i = 0; i < 2; ++i)                                                   \
            cp_async16(base + sBo[i], gB + (size_t)i * 64 * D_DIM + ke);              \
        CP_COMMIT();                                                                  \
    } while (0)

    LOAD_STAGE(0, 0); LOAD_STAGE(1, 1); LOAD_STAGE(2, 2);

    // ldmatrix lane addressing (precomputed row-dependent parts)
    const int aRow0 = warpM * 32 + (lane & 7) + ((lane >> 3) & 1) * 8;  // + mi*16
    const int bRow  = warpN * 64 + (lane & 7) + ((lane >> 3) & 1) * 8;  // + np*16
    const uint32_t kx = (lane >> 4) * 16;     // 0 or 16 bytes

    for (int t = 0; t < NKSTAGES; ++t) {
        CP_WAIT2();
        __syncthreads();
        const uint32_t base = sb + (uint32_t)(t % NSTAGE) * STG_BYTES;
#pragma unroll
        for (int ks = 0; ks < 4; ++ks) {              // 4 x k16
            const uint32_t kb = ks * 32;              // byte offset of k16 within 128B row
            uint32_t af[2][4];
#pragma unroll
            for (int mi = 0; mi < 2; ++mi) {
                const uint32_t r = aRow0 + mi * 16;
                ldmx4(af[mi], base + swz(r, kb + kx));
            }
#pragma unroll
            for (int np = 0; np < 4; ++np) {          // each covers ni = 2np, 2np+1
                uint32_t bf[4];
                const uint32_t r = bRow + np * 16;
                ldmx4(bf, base + A_STG + swz(r, kb + kx));
                mma_bf16(acc[0][2 * np],     af[0], bf[0], bf[2]);
                mma_bf16(acc[1][2 * np],     af[1], bf[0], bf[2]);
                mma_bf16(acc[0][2 * np + 1], af[0], bf[1], bf[3]);
                mma_bf16(acc[1][2 * np + 1], af[1], bf[1], bf[3]);
            }
        }
        if (t + 3 < NKSTAGES) LOAD_STAGE(t + 3, t + 3);
        __syncthreads();    // all warps done with stage t%NSTAGE before next overwrite
    }
    CP_WAIT0();
    __syncthreads();

    // ---- epilogue: epi[256][129] f32 (132KB, reuses stage smem), per-row top-2 ----
    float* epi = reinterpret_cast<float*>(smem);
    float* y2s = reinterpret_cast<float*>(smem + 256 * 129 * 4);
    if (tid < 128) y2s[tid] = g_y2[m0 + tid];
    const int fr = lane >> 2;
    const int fc = (lane & 3) * 2;
#pragma unroll
    for (int mi = 0; mi < 2; ++mi)
#pragma unroll
        for (int ni = 0; ni < 8; ++ni) {
            const int row = warpM * 32 + mi * 16 + fr;
            const int col = warpN * 64 + ni * 8 + fc;
            epi[row * 129 + col]           = acc[mi][ni][0];
            epi[row * 129 + col + 1]       = acc[mi][ni][1];
            epi[(row + 8) * 129 + col]     = acc[mi][ni][2];
            epi[(row + 8) * 129 + col + 1] = acc[mi][ni][3];
        }
    __syncthreads();
    if (tid < 256) {
        float tv0 = FLT_MAX, tv1 = FLT_MAX;
        int   ti0 = 0, ti1 = 0;
#pragma unroll 1
        for (int j = 0; j < 128; ++j) {
            const float v = y2s[j] - 2.f * epi[tid * 129 + j];
            const int idx = m0 + j;
            if (v < tv0)      { tv1 = tv0; ti1 = ti0; tv0 = v; ti0 = idx; }
            else if (v < tv1) { tv1 = v; ti1 = idx; }
        }
        Top2 t; t.v0 = tv0; t.v1 = tv1; t.i0 = ti0; t.i1 = ti1;
        g_top2[(size_t)(n0 + tid) * NCB + blockIdx.x] = t;
    }
}

// ---------------- K3: per-row candidate refinement in exact fp32 ----------------
__global__ void refine_kernel(const float* __restrict__ emb, const float* __restrict__ mb) {
    const int lane = threadIdx.x & 31;
    const int n = blockIdx.x * 8 + (threadIdx.x >> 5);

    float cv[8]; int ci[8];
    const Top2* tp = g_top2 + (size_t)n * NCB + lane * 4;
#pragma unroll
    for (int s = 0; s < 4; ++s) {
        Top2 t = tp[s];
        cv[2 * s]     = t.v0; ci[2 * s]     = t.i0;
        cv[2 * s + 1] = t.v1; ci[2 * s + 1] = t.i1;
    }
    int sel[8];
#pragma unroll 1
    for (int r = 0; r < 8; ++r) {       // top-8 of 256 candidates
        float bv = FLT_MAX; int bi = 0x7fffffff;
#pragma unroll
        for (int j = 0; j < 8; ++j)
            if (cv[j] < bv || (cv[j] == bv && ci[j] < bi)) { bv = cv[j]; bi = ci[j]; }
#pragma unroll
        for (int off = 16; off; off >>= 1) {
            float ov = __shfl_xor_sync(0xffffffffu, bv, off);
            int   oi = __shfl_xor_sync(0xffffffffu, bi, off);
            if (ov < bv || (ov == bv && oi < bi)) { bv = ov; bi = oi; }
        }
        sel[r] = bi;
#pragma unroll
        for (int j = 0; j < 8; ++j)
            if (ci[j] == bi) cv[j] = FLT_MAX;
    }
    float4 xl[12];
    const float4* x4 = reinterpret_cast<const float4*>(emb) + (size_t)n * (D_DIM / 4);
#pragma unroll
    for (int j = 0; j < 12; ++j) xl[j] = x4[lane + j * 32];
    const float xn = g_x2[n];
    float bestd = FLT_MAX; int besti = 0x7fffffff;
#pragma unroll 1
    for (int r = 0; r < 8; ++r) {
        const int m = sel[r];
        const float4* y4 = reinterpret_cast<const float4*>(mb) + (size_t)m * (D_DIM / 4);
        float s = 0.f;
#pragma unroll
        for (int j = 0; j < 12; ++j) {
            float4 bv = y4[lane + j * 32];
            s += xl[j].x * bv.x + xl[j].y * bv.y + xl[j].z * bv.z + xl[j].w * bv.w;
        }
#pragma unroll
        for (int off = 16; off; off >>= 1) s += __shfl_xor_sync(0xffffffffu, s, off);
        const float d2 = xn + g_y2[m] - 2.f * s;
        if (d2 < bestd || (d2 == bestd && m < besti)) { bestd = d2; besti = m; }
    }
    if (lane == 0) {
        g_pscore[n] = sqrtf(fmaxf(bestd, 0.f));
        g_ploc[n]   = besti;
    }
}

// ---------------- K4: per-batch argmax over patch scores ----------------
__global__ void argmax_kernel() {
    const int b = blockIdx.x;
    const int base = b * P_PT;
    const int tid = threadIdx.x;
    float bv = -FLT_MAX; int bi = 0x7fffffff;
    for (int i = tid; i < P_PT; i += 256) {
        const float v = g_pscore[base + i];
        if (v > bv || (v == bv && i < bi)) { bv = v; bi = i; }
    }
    __shared__ float sv[256]; __shared__ int si[256];
    sv[tid] = bv; si[tid] = bi;
    __syncthreads();
    for (int s = 128; s; s >>= 1) {
        if (tid < s) {
            if (sv[tid + s] > sv[tid] || (sv[tid + s] == sv[tid] && si[tid + s] < si[tid])) {
                sv[tid] = sv[tid + s]; si[tid] = si[tid + s];
            }
        }
        __syncthreads();
    }
    if (tid == 0) {
        const int n = base + si[0];
        g_bscore[b] = sv[0];
        g_bn[b]     = n;
        g_bnn[b]    = g_ploc[n];
    }
}

// ---------------- K5: fp32 distances nn_sample[b] <-> memory_bank ----------------
__global__ void stage2_kernel(const float* __restrict__ mb) {
    const int lane = threadIdx.x & 31;
    const int m = blockIdx.x * 8 + (threadIdx.x >> 5);
    const float4* y4 = reinterpret_cast<const float4*>(mb) + (size_t)m * (D_DIM / 4);
    float4 yl[12];
#pragma unroll
    for (int j = 0; j < 12; ++j) yl[j] = y4[lane + j * 32];
    const float ym = g_y2[m];
#pragma unroll 1
    for (int b = 0; b < B_SZ; ++b) {
        const int nn = g_bnn[b];
        const float4* x4 = reinterpret_cast<const float4*>(mb) + (size_t)nn * (D_DIM / 4);
        float s = 0.f;
#pragma unroll
        for (int j = 0; j < 12; ++j) {
            float4 a = x4[lane + j * 32];
            s += yl[j].x * a.x + yl[j].y * a.y + yl[j].z * a.z + yl[j].w * a.w;
        }
#pragma unroll
        for (int off = 16; off; off >>= 1) s += __shfl_xor_sync(0xffffffffu, s, off);
        if (lane == 0) g_d2b[(size_t)b * M_MB + m] = g_y2[nn] + ym - 2.f * s;
    }
}

// ---------------- K6: top-9 support, softmax re-weighting, output ----------------
__global__ void finalize_kernel(const float* __restrict__ emb, const float* __restrict__ mb,
                                float* __restrict__ out) {
    const int b = blockIdx.x;
    const int tid = threadIdx.x;
    __shared__ int sel[9];
    __shared__ float dist9[9];
    __shared__ float rv[256]; __shared__ int ri[256];
    const float* d2 = g_d2b + (size_t)b * M_MB;

    for (int j = 0; j < 9; ++j) {
        float bv = FLT_MAX; int bi = 0x7fffffff;
        for (int m = tid; m < M_MB; m += 256) {
            bool used = false;
            for (int q = 0; q < j; ++q) used |= (sel[q] == m);
            const float v = d2[m];
            if (!used && (v < bv || (v == bv && m < bi))) { bv = v; bi = m; }
        }
        rv[tid] = bv; ri[tid] = bi;
        __syncthreads();
        for (int s = 128; s; s >>= 1) {
            if (tid < s) {
                if (rv[tid + s] < rv[tid] || (rv[tid + s] == rv[tid] && ri[tid + s] < ri[tid])) {
                    rv[tid] = rv[tid + s]; ri[tid] = ri[tid + s];
                }
            }
            __syncthreads();
        }
        if (tid == 0) sel[j] = ri[0];
        __syncthreads();
    }

    const float* xp = emb + (size_t)g_bn[b] * D_DIM;
    for (int j = 0; j < 9; ++j) {
        const float* y = mb + (size_t)sel[j] * D_DIM;
        float s = 0.f;
        for (int k = tid; k < D_DIM; k += 256) { const float df = xp[k] - y[k]; s += df * df; }
        rv[tid] = s;
        __syncthreads();
        for (int st = 128; st; st >>= 1) {
            if (tid < st) rv[tid] += rv[tid + st];
            __syncthreads();
        }
        if (tid == 0) dist9[j] = sqrtf(fmaxf(rv[0], 0.f));
        __syncthreads();
    }
    if (tid == 0) {
        float mx = dist9[0];
        for (int j = 1; j < 9; ++j) mx = fmaxf(mx, dist9[j]);
        float sum = 0.f, e0 = 0.f;
        for (int j = 0; j < 9; ++j) {
            const float e = expf(dist9[j] - mx);
            if (j == 0) e0 = e;
            sum += e;
        }
        out[b] = (1.f - e0 / sum) * g_bscore[b];
    }
}

// ---------------- launch ----------------
extern "C" void kernel_launch(void* const* d_in, const int* in_sizes, int n_in,
                              void* d_out, int out_size) {
    const float* emb = (const float*)d_in[0];
    const float* mb  = (const float*)d_in[1];
    float* out = (float*)d_out;

    static bool s_attr_set = false;
    if (!s_attr_set) {
        cudaFuncSetAttribute(gemm_min_kernel, cudaFuncAttributeMaxDynamicSharedMemorySize,
                             GEMM_SMEM);
        s_attr_set = true;
    }

    prep_kernel<<<N_EMB, 128>>>(emb, 0);
    prep_kernel<<<M_MB, 128>>>(mb, 1);
    gemm_min_kernel<<<dim3(NCB, N_EMB / 256), 512, GEMM_SMEM>>>();
    refine_kernel<<<N_EMB / 8, 256>>>(emb, mb);
    argmax_kernel<<<B_SZ, 256>>>();
    stage2_kernel<<<B_SZ == 0 ? 1 : M_MB / 8, 256>>>(mb);
    finalize_kernel<<<B_SZ, 256>>>(emb, mb, out);
}

// round 6
// speedup vs baseline: 2.1095x; 1.5407x over previous
#include <cuda_runtime.h>
#include <cuda_bf16.h>
#include <cstdint>
#include <cfloat>

#define N_EMB 12544
#define M_MB  16384
#define D_DIM 1536
#define B_SZ  16
#define P_PT  (N_EMB / B_SZ)     // 784
#define NCB   (M_MB / 128)       // 128 column blocks
#define KSTAGE 128                // int8 elements per stage = 128B rows
#define NKSTAGES (D_DIM / KSTAGE) // 12
#define NSTAGE 4
#define A_STG 32768               // 256 rows x 128B
#define B_STG 16384               // 128 rows x 128B
#define STG_BYTES (A_STG + B_STG) // 49152
#define GEMM_SMEM (NSTAGE * STG_BYTES)  // 196608
#define QSCALE 32.0f
#define D2SCALE (2.0f / (QSCALE * QSCALE))   // 2/1024

// ---------------- device scratch (static: no allocations allowed) ----------------
__device__ int8_t g_embQ[(size_t)N_EMB * D_DIM];          // 19.3 MB
__device__ int8_t g_mbQ[(size_t)M_MB * D_DIM];            // 25.2 MB
__device__ float g_x2[N_EMB];
__device__ float g_y2[M_MB];
struct __align__(16) Top2 { float v0, v1; int i0, i1; };
__device__ Top2 g_top2[(size_t)N_EMB * NCB];              // 25.7 MB
__device__ float g_pscore[N_EMB];
__device__ int   g_ploc[N_EMB];
__device__ float g_bscore[B_SZ];
__device__ int   g_bn[B_SZ];
__device__ int   g_bnn[B_SZ];
__device__ float g_d2b[(size_t)B_SZ * M_MB];              // 1 MB

// ---------------- helpers ----------------
__device__ __forceinline__ uint32_t smem_u32(const void* p) {
    uint32_t a;
    asm("{ .reg .u64 t; cvta.to.shared.u64 t, %1; cvt.u32.u64 %0, t; }" : "=r"(a) : "l"(p));
    return a;
}
__device__ __forceinline__ void cp_async16(uint32_t saddr, const void* gaddr) {
    asm volatile("cp.async.cg.shared.global [%0], [%1], 16;" :: "r"(saddr), "l"(gaddr) : "memory");
}
#define CP_COMMIT() asm volatile("cp.async.commit_group;" ::: "memory")
#define CP_WAIT2()  asm volatile("cp.async.wait_group 2;" ::: "memory")
#define CP_WAIT0()  asm volatile("cp.async.wait_group 0;" ::: "memory")
__device__ __forceinline__ void ldmx4(uint32_t* r, uint32_t addr) {
    asm volatile("ldmatrix.sync.aligned.m8n8.x4.shared.b16 {%0,%1,%2,%3}, [%4];"
                 : "=r"(r[0]), "=r"(r[1]), "=r"(r[2]), "=r"(r[3]) : "r"(addr));
}
__device__ __forceinline__ void mma_s8(int* c, const uint32_t* a, uint32_t b0, uint32_t b1) {
    asm volatile(
        "mma.sync.aligned.m16n8k32.row.col.s32.s8.s8.s32 "
        "{%0,%1,%2,%3}, {%4,%5,%6,%7}, {%8,%9}, {%0,%1,%2,%3};\n"
        : "+r"(c[0]), "+r"(c[1]), "+r"(c[2]), "+r"(c[3])
        : "r"(a[0]), "r"(a[1]), "r"(a[2]), "r"(a[3]), "r"(b0), "r"(b1));
}
// swizzle: 128B rows, XOR 16B-chunk by row%8 (conflict-free ldmatrix + cp.async)
__device__ __forceinline__ uint32_t swz(uint32_t row, uint32_t kbyte) {
    return row * 128 + (kbyte ^ ((row & 7) << 4));
}
__device__ __forceinline__ int8_t quant1(float v) {
    int q = __float2int_rn(v * QSCALE);
    q = max(-127, min(127, q));
    return (int8_t)q;
}

// ---------------- K1: fp32 -> int8 quantization + row squared norms ----------------
__global__ void prep_kernel(const float* __restrict__ src, int which) {
    const int row = blockIdx.x;
    const float4* s = reinterpret_cast<const float4*>(src) + (size_t)row * (D_DIM / 4);
    char4* d = reinterpret_cast<char4*>(which ? g_mbQ : g_embQ) + (size_t)row * (D_DIM / 4);
    float acc = 0.f;
    for (int i = threadIdx.x; i < D_DIM / 4; i += blockDim.x) {
        float4 v = s[i];
        acc += v.x * v.x + v.y * v.y + v.z * v.z + v.w * v.w;
        char4 q;
        q.x = quant1(v.x); q.y = quant1(v.y); q.z = quant1(v.z); q.w = quant1(v.w);
        d[i] = q;
    }
#pragma unroll
    for (int off = 16; off; off >>= 1) acc += __shfl_xor_sync(0xffffffffu, acc, off);
    __shared__ float ws[4];
    if ((threadIdx.x & 31) == 0) ws[threadIdx.x >> 5] = acc;
    __syncthreads();
    if (threadIdx.x == 0) {
        float t = ws[0] + ws[1] + ws[2] + ws[3];
        if (which) g_y2[row] = t; else g_x2[row] = t;
    }
}

// ---------------- K2: pipelined s8 IMMA GEMM 256n x 128m + top-2 epilogue ----------------
__global__ void __launch_bounds__(256, 1)
gemm_min_kernel() {
    extern __shared__ __align__(1024) unsigned char smem[];
    const uint32_t sb = smem_u32(smem);
    const int tid = threadIdx.x;
    const int lane = tid & 31;
    const int warp = tid >> 5;
    const int warpM = warp & 3;      // 4 row-warps (64 emb rows each)
    const int warpN = warp >> 2;     // 2 col-warps (64 mb cols each)
    const int m0 = blockIdx.x * 128; // memory-bank columns
    const int n0 = blockIdx.y * 256; // embedding rows

    int acc[4][8][4];
#pragma unroll
    for (int mi = 0; mi < 4; ++mi)
#pragma unroll
        for (int ni = 0; ni < 8; ++ni)
#pragma unroll
            for (int q = 0; q < 4; ++q) acc[mi][ni][q] = 0;

    // cp.async: A 256 rows (8 per thread), B 128 rows (4 per thread); 16B chunks
    const int crow = tid >> 3;            // 0..31
    const int cchk = tid & 7;             // 16B chunk within 128B row
    const int8_t* gA = g_embQ + (size_t)(n0 + crow) * D_DIM + cchk * 16;
    const int8_t* gB = g_mbQ  + (size_t)(m0 + crow) * D_DIM + cchk * 16;
    uint32_t sAo[8], sBo[4];
#pragma unroll
    for (int i = 0; i < 8; ++i) sAo[i] = swz(crow + i * 32, cchk * 16);
#pragma unroll
    for (int i = 0; i < 4; ++i) sBo[i] = A_STG + swz(crow + i * 32, cchk * 16);

#define LOAD_STAGE(s, t)                                                              \
    do {                                                                              \
        const uint32_t base = sb + (uint32_t)((s) % NSTAGE) * STG_BYTES;              \
        const size_t ke = (size_t)(t) * KSTAGE;                                       \
        _Pragma("unroll")                                                             \
        for (int i = 0; i < 8; ++i)                                                   \
            cp_async16(base + sAo[i], gA + (size_t)i * 32 * D_DIM + ke);              \
        _Pragma("unroll")                                                             \
        for (int i = 0; i < 4; ++i)                                                   \
            cp_async16(base + sBo[i], gB + (size_t)i * 32 * D_DIM + ke);              \
        CP_COMMIT();                                                                  \
    } while (0)

    LOAD_STAGE(0, 0); LOAD_STAGE(1, 1); LOAD_STAGE(2, 2);

    // ldmatrix lane addressing: tile = lane>>3 -> (row+8*(bit0), kbyte+16*(bit1))
    const int aRow0 = warpM * 64 + (lane & 7) + ((lane >> 3) & 1) * 8;  // + mi*16
    const int bRow  = warpN * 64 + (lane & 7) + ((lane >> 3) & 1) * 8;  // + np*16
    const uint32_t kx = (lane >> 4) * 16;     // 0 or 16 bytes

    for (int t = 0; t < NKSTAGES; ++t) {
        CP_WAIT2();
        __syncthreads();
        const uint32_t base = sb + (uint32_t)(t % NSTAGE) * STG_BYTES;
#pragma unroll
        for (int ks = 0; ks < 4; ++ks) {              // 4 x k32
            const uint32_t kb = ks * 32;              // byte offset of k32 within 128B row
            uint32_t af[4][4];
#pragma unroll
            for (int mi = 0; mi < 4; ++mi)
                ldmx4(af[mi], base + swz(aRow0 + mi * 16, kb + kx));
#pragma unroll
            for (int np = 0; np < 4; ++np) {          // each covers ni = 2np, 2np+1
                uint32_t bf[4];
                ldmx4(bf, base + A_STG + swz(bRow + np * 16, kb + kx));
#pragma unroll
                for (int mi = 0; mi < 4; ++mi) {
                    mma_s8(acc[mi][2 * np],     af[mi], bf[0], bf[2]);
                    mma_s8(acc[mi][2 * np + 1], af[mi], bf[1], bf[3]);
                }
            }
        }
        if (t + 3 < NKSTAGES) LOAD_STAGE(t + 3, t + 3);
        __syncthreads();    // all warps done with stage t%NSTAGE before next overwrite
    }
    CP_WAIT0();
    __syncthreads();

    // ---- epilogue: epi[256][129] f32 (132KB, reuses stage smem), per-row top-2 ----
    float* epi = reinterpret_cast<float*>(smem);
    float* y2s = reinterpret_cast<float*>(smem + 256 * 129 * 4);
    if (tid < 128) y2s[tid] = g_y2[m0 + tid];
    const int fr = lane >> 2;
    const int fc = (lane & 3) * 2;
#pragma unroll
    for (int mi = 0; mi < 4; ++mi)
#pragma unroll
        for (int ni = 0; ni < 8; ++ni) {
            const int row = warpM * 64 + mi * 16 + fr;
            const int col = warpN * 64 + ni * 8 + fc;
            epi[row * 129 + col]           = (float)acc[mi][ni][0];
            epi[row * 129 + col + 1]       = (float)acc[mi][ni][1];
            epi[(row + 8) * 129 + col]     = (float)acc[mi][ni][2];
            epi[(row + 8) * 129 + col + 1] = (float)acc[mi][ni][3];
        }
    __syncthreads();
    // 256 threads, one row each
    {
        float tv0 = FLT_MAX, tv1 = FLT_MAX;
        int   ti0 = 0, ti1 = 0;
#pragma unroll 1
        for (int j = 0; j < 128; ++j) {
            const float v = y2s[j] - D2SCALE * epi[tid * 129 + j];
            const int idx = m0 + j;
            if (v < tv0)      { tv1 = tv0; ti1 = ti0; tv0 = v; ti0 = idx; }
            else if (v < tv1) { tv1 = v; ti1 = idx; }
        }
        Top2 t; t.v0 = tv0; t.v1 = tv1; t.i0 = ti0; t.i1 = ti1;
        g_top2[(size_t)(n0 + tid) * NCB + blockIdx.x] = t;
    }
}

// ---------------- K3: per-row candidate refinement in exact fp32 ----------------
__global__ void refine_kernel(const float* __restrict__ emb, const float* __restrict__ mb) {
    const int lane = threadIdx.x & 31;
    const int n = blockIdx.x * 8 + (threadIdx.x >> 5);

    float cv[8]; int ci[8];
    const Top2* tp = g_top2 + (size_t)n * NCB + lane * 4;
#pragma unroll
    for (int s = 0; s < 4; ++s) {
        Top2 t = tp[s];
        cv[2 * s]     = t.v0; ci[2 * s]     = t.i0;
        cv[2 * s + 1] = t.v1; ci[2 * s + 1] = t.i1;
    }
    int sel[8];
#pragma unroll 1
    for (int r = 0; r < 8; ++r) {       // top-8 of 256 candidates
        float bv = FLT_MAX; int bi = 0x7fffffff;
#pragma unroll
        for (int j = 0; j < 8; ++j)
            if (cv[j] < bv || (cv[j] == bv && ci[j] < bi)) { bv = cv[j]; bi = ci[j]; }
#pragma unroll
        for (int off = 16; off; off >>= 1) {
            float ov = __shfl_xor_sync(0xffffffffu, bv, off);
            int   oi = __shfl_xor_sync(0xffffffffu, bi, off);
            if (ov < bv || (ov == bv && oi < bi)) { bv = ov; bi = oi; }
        }
        sel[r] = bi;
#pragma unroll
        for (int j = 0; j < 8; ++j)
            if (ci[j] == bi) cv[j] = FLT_MAX;
    }
    float4 xl[12];
    const float4* x4 = reinterpret_cast<const float4*>(emb) + (size_t)n * (D_DIM / 4);
#pragma unroll
    for (int j = 0; j < 12; ++j) xl[j] = x4[lane + j * 32];
    const float xn = g_x2[n];
    float bestd = FLT_MAX; int besti = 0x7fffffff;
#pragma unroll 1
    for (int r = 0; r < 8; ++r) {
        const int m = sel[r];
        const float4* y4 = reinterpret_cast<const float4*>(mb) + (size_t)m * (D_DIM / 4);
        float s = 0.f;
#pragma unroll
        for (int j = 0; j < 12; ++j) {
            float4 bv = y4[lane + j * 32];
            s += xl[j].x * bv.x + xl[j].y * bv.y + xl[j].z * bv.z + xl[j].w * bv.w;
        }
#pragma unroll
        for (int off = 16; off; off >>= 1) s += __shfl_xor_sync(0xffffffffu, s, off);
        const float d2 = xn + g_y2[m] - 2.f * s;
        if (d2 < bestd || (d2 == bestd && m < besti)) { bestd = d2; besti = m; }
    }
    if (lane == 0) {
        g_pscore[n] = sqrtf(fmaxf(bestd, 0.f));
        g_ploc[n]   = besti;
    }
}

// ---------------- K4: per-batch argmax over patch scores ----------------
__global__ void argmax_kernel() {
    const int b = blockIdx.x;
    const int base = b * P_PT;
    const int tid = threadIdx.x;
    float bv = -FLT_MAX; int bi = 0x7fffffff;
    for (int i = tid; i < P_PT; i += 256) {
        const float v = g_pscore[base + i];
        if (v > bv || (v == bv && i < bi)) { bv = v; bi = i; }
    }
    __shared__ float sv[256]; __shared__ int si[256];
    sv[tid] = bv; si[tid] = bi;
    __syncthreads();
    for (int s = 128; s; s >>= 1) {
        if (tid < s) {
            if (sv[tid + s] > sv[tid] || (sv[tid + s] == sv[tid] && si[tid + s] < si[tid])) {
                sv[tid] = sv[tid + s]; si[tid] = si[tid + s];
            }
        }
        __syncthreads();
    }
    if (tid == 0) {
        const int n = base + si[0];
        g_bscore[b] = sv[0];
        g_bn[b]     = n;
        g_bnn[b]    = g_ploc[n];
    }
}

// ---------------- K5: fp32 distances nn_sample[b] <-> memory_bank ----------------
__global__ void stage2_kernel(const float* __restrict__ mb) {
    const int lane = threadIdx.x & 31;
    const int m = blockIdx.x * 8 + (threadIdx.x >> 5);
    const float4* y4 = reinterpret_cast<const float4*>(mb) + (size_t)m * (D_DIM / 4);
    float4 yl[12];
#pragma unroll
    for (int j = 0; j < 12; ++j) yl[j] = y4[lane + j * 32];
    const float ym = g_y2[m];
#pragma unroll 1
    for (int b = 0; b < B_SZ; ++b) {
        const int nn = g_bnn[b];
        const float4* x4 = reinterpret_cast<const float4*>(mb) + (size_t)nn * (D_DIM / 4);
        float s = 0.f;
#pragma unroll
        for (int j = 0; j < 12; ++j) {
            float4 a = x4[lane + j * 32];
            s += yl[j].x * a.x + yl[j].y * a.y + yl[j].z * a.z + yl[j].w * a.w;
        }
#pragma unroll
        for (int off = 16; off; off >>= 1) s += __shfl_xor_sync(0xffffffffu, s, off);
        if (lane == 0) g_d2b[(size_t)b * M_MB + m] = g_y2[nn] + ym - 2.f * s;
    }
}

// ---------------- K6: top-9 support, softmax re-weighting, output ----------------
__global__ void finalize_kernel(const float* __restrict__ emb, const float* __restrict__ mb,
                                float* __restrict__ out) {
    const int b = blockIdx.x;
    const int tid = threadIdx.x;
    __shared__ int sel[9];
    __shared__ float dist9[9];
    __shared__ float rv[256]; __shared__ int ri[256];
    const float* d2 = g_d2b + (size_t)b * M_MB;

    for (int j = 0; j < 9; ++j) {
        float bv = FLT_MAX; int bi = 0x7fffffff;
        for (int m = tid; m < M_MB; m += 256) {
            bool used = false;
            for (int q = 0; q < j; ++q) used |= (sel[q] == m);
            const float v = d2[m];
            if (!used && (v < bv || (v == bv && m < bi))) { bv = v; bi = m; }
        }
        rv[tid] = bv; ri[tid] = bi;
        __syncthreads();
        for (int s = 128; s; s >>= 1) {
            if (tid < s) {
                if (rv[tid + s] < rv[tid] || (rv[tid + s] == rv[tid] && ri[tid + s] < ri[tid])) {
                    rv[tid] = rv[tid + s]; ri[tid] = ri[tid + s];
                }
            }
            __syncthreads();
        }
        if (tid == 0) sel[j] = ri[0];
        __syncthreads();
    }

    const float* xp = emb + (size_t)g_bn[b] * D_DIM;
    for (int j = 0; j < 9; ++j) {
        const float* y = mb + (size_t)sel[j] * D_DIM;
        float s = 0.f;
        for (int k = tid; k < D_DIM; k += 256) { const float df = xp[k] - y[k]; s += df * df; }
        rv[tid] = s;
        __syncthreads();
        for (int st = 128; st; st >>= 1) {
            if (tid < st) rv[tid] += rv[tid + st];
            __syncthreads();
        }
        if (tid == 0) dist9[j] = sqrtf(fmaxf(rv[0], 0.f));
        __syncthreads();
    }
    if (tid == 0) {
        float mx = dist9[0];
        for (int j = 1; j < 9; ++j) mx = fmaxf(mx, dist9[j]);
        float sum = 0.f, e0 = 0.f;
        for (int j = 0; j < 9; ++j) {
            const float e = expf(dist9[j] - mx);
            if (j == 0) e0 = e;
            sum += e;
        }
        out[b] = (1.f - e0 / sum) * g_bscore[b];
    }
}

// ---------------- launch ----------------
extern "C" void kernel_launch(void* const* d_in, const int* in_sizes, int n_in,
                              void* d_out, int out_size) {
    const float* emb = (const float*)d_in[0];
    const float* mb  = (const float*)d_in[1];
    float* out = (float*)d_out;

    static bool s_attr_set = false;
    if (!s_attr_set) {
        cudaFuncSetAttribute(gemm_min_kernel, cudaFuncAttributeMaxDynamicSharedMemorySize,
                             GEMM_SMEM);
        s_attr_set = true;
    }

    prep_kernel<<<N_EMB, 128>>>(emb, 0);
    prep_kernel<<<M_MB, 128>>>(mb, 1);
    gemm_min_kernel<<<dim3(NCB, N_EMB / 256), 256, GEMM_SMEM>>>();
    refine_kernel<<<N_EMB / 8, 256>>>(emb, mb);
    argmax_kernel<<<B_SZ, 256>>>();
    stage2_kernel<<<M_MB / 8, 256>>>(mb);
    finalize_kernel<<<B_SZ, 256>>>(emb, mb, out);
}

// round 7
// speedup vs baseline: 2.1240x; 1.0068x over previous
#include <cuda_runtime.h>
#include <cuda_bf16.h>
#include <cstdint>
#include <cfloat>

#define N_EMB 12544
#define M_MB  16384
#define D_DIM 1536
#define B_SZ  16
#define P_PT  (N_EMB / B_SZ)     // 784
#define NCB   (M_MB / 128)       // 128 column blocks
#define KSTAGE 128                // int8 elements per stage = 128B rows
#define NKSTAGES (D_DIM / KSTAGE) // 12
#define NSTAGE 4
#define A_STG 32768               // 256 rows x 128B
#define B_STG 16384               // 128 rows x 128B
#define STG_BYTES (A_STG + B_STG) // 49152
#define GEMM_SMEM (NSTAGE * STG_BYTES)  // 196608
#define QSCALE 32.0f
#define D2SCALE (2.0f / (QSCALE * QSCALE))   // 2/1024

// ---------------- device scratch (static: no allocations allowed) ----------------
__device__ int8_t g_embQ[(size_t)N_EMB * D_DIM];          // 19.3 MB
__device__ int8_t g_mbQ[(size_t)M_MB * D_DIM];            // 25.2 MB
__device__ float g_x2[N_EMB];
__device__ float g_y2[M_MB];
struct __align__(16) Top2 { float v0, v1; int i0, i1; };
__device__ Top2 g_top2[(size_t)N_EMB * NCB];              // 25.7 MB
__device__ float g_pscore[N_EMB];
__device__ int   g_ploc[N_EMB];
__device__ float g_bscore[B_SZ];
__device__ int   g_bn[B_SZ];
__device__ int   g_bnn[B_SZ];
__device__ float g_d2b[(size_t)B_SZ * M_MB];              // 1 MB

// ---------------- helpers ----------------
__device__ __forceinline__ uint32_t smem_u32(const void* p) {
    uint32_t a;
    asm("{ .reg .u64 t; cvta.to.shared.u64 t, %1; cvt.u32.u64 %0, t; }" : "=r"(a) : "l"(p));
    return a;
}
__device__ __forceinline__ void cp_async16(uint32_t saddr, const void* gaddr) {
    asm volatile("cp.async.cg.shared.global [%0], [%1], 16;" :: "r"(saddr), "l"(gaddr) : "memory");
}
#define CP_COMMIT() asm volatile("cp.async.commit_group;" ::: "memory")
#define CP_WAIT2()  asm volatile("cp.async.wait_group 2;" ::: "memory")
#define CP_WAIT0()  asm volatile("cp.async.wait_group 0;" ::: "memory")
__device__ __forceinline__ void ldmx4(uint32_t* r, uint32_t addr) {
    asm volatile("ldmatrix.sync.aligned.m8n8.x4.shared.b16 {%0,%1,%2,%3}, [%4];"
                 : "=r"(r[0]), "=r"(r[1]), "=r"(r[2]), "=r"(r[3]) : "r"(addr));
}
__device__ __forceinline__ void mma_s8(int* c, const uint32_t* a, uint32_t b0, uint32_t b1) {
    asm volatile(
        "mma.sync.aligned.m16n8k32.row.col.s32.s8.s8.s32 "
        "{%0,%1,%2,%3}, {%4,%5,%6,%7}, {%8,%9}, {%0,%1,%2,%3};\n"
        : "+r"(c[0]), "+r"(c[1]), "+r"(c[2]), "+r"(c[3])
        : "r"(a[0]), "r"(a[1]), "r"(a[2]), "r"(a[3]), "r"(b0), "r"(b1));
}
// swizzle: 128B rows, XOR 16B-chunk by row%8 (conflict-free ldmatrix + cp.async)
__device__ __forceinline__ uint32_t swz(uint32_t row, uint32_t kbyte) {
    return row * 128 + (kbyte ^ ((row & 7) << 4));
}
__device__ __forceinline__ int8_t quant1(float v) {
    int q = __float2int_rn(v * QSCALE);
    q = max(-127, min(127, q));
    return (int8_t)q;
}

// ---------------- K1: fp32 -> int8 quantization + row squared norms ----------------
__global__ void prep_kernel(const float* __restrict__ src, int which) {
    const int row = blockIdx.x;
    const float4* s = reinterpret_cast<const float4*>(src) + (size_t)row * (D_DIM / 4);
    char4* d = reinterpret_cast<char4*>(which ? g_mbQ : g_embQ) + (size_t)row * (D_DIM / 4);
    float acc = 0.f;
    for (int i = threadIdx.x; i < D_DIM / 4; i += blockDim.x) {
        float4 v = s[i];
        acc += v.x * v.x + v.y * v.y + v.z * v.z + v.w * v.w;
        char4 q;
        q.x = quant1(v.x); q.y = quant1(v.y); q.z = quant1(v.z); q.w = quant1(v.w);
        d[i] = q;
    }
#pragma unroll
    for (int off = 16; off; off >>= 1) acc += __shfl_xor_sync(0xffffffffu, acc, off);
    __shared__ float ws[4];
    if ((threadIdx.x & 31) == 0) ws[threadIdx.x >> 5] = acc;
    __syncthreads();
    if (threadIdx.x == 0) {
        float t = ws[0] + ws[1] + ws[2] + ws[3];
        if (which) g_y2[row] = t; else g_x2[row] = t;
    }
}

// ---------------- K2: pipelined s8 IMMA GEMM 256n x 128m + top-2 epilogue ----------------
__global__ void __launch_bounds__(256, 1)
gemm_min_kernel() {
    extern __shared__ __align__(1024) unsigned char smem[];
    const uint32_t sb = smem_u32(smem);
    const int tid = threadIdx.x;
    const int lane = tid & 31;
    const int warp = tid >> 5;
    const int warpM = warp & 3;      // 4 row-warps (64 emb rows each)
    const int warpN = warp >> 2;     // 2 col-warps (64 mb cols each)
    const int m0 = blockIdx.x * 128; // memory-bank columns
    const int n0 = blockIdx.y * 256; // embedding rows

    int acc[4][8][4];
#pragma unroll
    for (int mi = 0; mi < 4; ++mi)
#pragma unroll
        for (int ni = 0; ni < 8; ++ni)
#pragma unroll
            for (int q = 0; q < 4; ++q) acc[mi][ni][q] = 0;

    // cp.async: A 256 rows (8 per thread), B 128 rows (4 per thread); 16B chunks
    const int crow = tid >> 3;            // 0..31
    const int cchk = tid & 7;             // 16B chunk within 128B row
    const int8_t* gA = g_embQ + (size_t)(n0 + crow) * D_DIM + cchk * 16;
    const int8_t* gB = g_mbQ  + (size_t)(m0 + crow) * D_DIM + cchk * 16;
    uint32_t sAo[8], sBo[4];
#pragma unroll
    for (int i = 0; i < 8; ++i) sAo[i] = swz(crow + i * 32, cchk * 16);
#pragma unroll
    for (int i = 0; i < 4; ++i) sBo[i] = A_STG + swz(crow + i * 32, cchk * 16);

#define LOAD_STAGE(s, t)                                                              \
    do {                                                                              \
        const uint32_t base = sb + (uint32_t)((s) % NSTAGE) * STG_BYTES;              \
        const size_t ke = (size_t)(t) * KSTAGE;                                       \
        _Pragma("unroll")                                                             \
        for (int i = 0; i < 8; ++i)                                                   \
            cp_async16(base + sAo[i], gA + (size_t)i * 32 * D_DIM + ke);              \
        _Pragma("unroll")                                                             \
        for (int i = 0; i < 4; ++i)                                                   \
            cp_async16(base + sBo[i], gB + (size_t)i * 32 * D_DIM + ke);              \
        CP_COMMIT();                                                                  \
    } while (0)

    LOAD_STAGE(0, 0); LOAD_STAGE(1, 1); LOAD_STAGE(2, 2);

    // ldmatrix lane addressing: tile = lane>>3 -> (row+8*(bit0), kbyte+16*(bit1))
    const int aRow0 = warpM * 64 + (lane & 7) + ((lane >> 3) & 1) * 8;  // + mi*16
    const int bRow  = warpN * 64 + (lane & 7) + ((lane >> 3) & 1) * 8;  // + np*16
    const uint32_t kx = (lane >> 4) * 16;     // 0 or 16 bytes

    uint32_t af[4][4];        // A frags for current k-step
    uint32_t bf[2][4][4];     // B frags, double-buffered across k-steps

    for (int t = 0; t < NKSTAGES; ++t) {
        CP_WAIT2();
        __syncthreads();
        const uint32_t base = sb + (uint32_t)(t % NSTAGE) * STG_BYTES;

        // prime: B frags for k-step 0 of this stage
#pragma unroll
        for (int np = 0; np < 4; ++np)
            ldmx4(bf[0][np], base + A_STG + swz(bRow + np * 16, kx));

#pragma unroll
        for (int ks = 0; ks < 4; ++ks) {              // 4 x k32
            const uint32_t kb = ks * 32;              // byte offset of k32 within 128B row
            const int cur = ks & 1;
            // A frags for this k-step (batched; latency overlapped with B-next + IMMAs)
#pragma unroll
            for (int mi = 0; mi < 4; ++mi)
                ldmx4(af[mi], base + swz(aRow0 + mi * 16, kb + kx));
            // B frags for NEXT k-step issue before the IMMA block consumes this one
            if (ks < 3) {
#pragma unroll
                for (int np = 0; np < 4; ++np)
                    ldmx4(bf[cur ^ 1][np], base + A_STG + swz(bRow + np * 16, kb + 32 + kx));
            }
#pragma unroll
            for (int np = 0; np < 4; ++np) {          // each covers ni = 2np, 2np+1
#pragma unroll
                for (int mi = 0; mi < 4; ++mi) {
                    mma_s8(acc[mi][2 * np],     af[mi], bf[cur][np][0], bf[cur][np][2]);
                    mma_s8(acc[mi][2 * np + 1], af[mi], bf[cur][np][1], bf[cur][np][3]);
                }
            }
        }
        if (t + 3 < NKSTAGES) LOAD_STAGE(t + 3, t + 3);
        __syncthreads();    // all warps done with stage t%NSTAGE before next overwrite
    }
    CP_WAIT0();
    __syncthreads();

    // ---- epilogue: epi[256][129] f32 (132KB, reuses stage smem), per-row top-2 ----
    float* epi = reinterpret_cast<float*>(smem);
    float* y2s = reinterpret_cast<float*>(smem + 256 * 129 * 4);
    if (tid < 128) y2s[tid] = g_y2[m0 + tid];
    const int fr = lane >> 2;
    const int fc = (lane & 3) * 2;
#pragma unroll
    for (int mi = 0; mi < 4; ++mi)
#pragma unroll
        for (int ni = 0; ni < 8; ++ni) {
            const int row = warpM * 64 + mi * 16 + fr;
            const int col = warpN * 64 + ni * 8 + fc;
            epi[row * 129 + col]           = (float)acc[mi][ni][0];
            epi[row * 129 + col + 1]       = (float)acc[mi][ni][1];
            epi[(row + 8) * 129 + col]     = (float)acc[mi][ni][2];
            epi[(row + 8) * 129 + col + 1] = (float)acc[mi][ni][3];
        }
    __syncthreads();
    // 256 threads, one row each
    {
        float tv0 = FLT_MAX, tv1 = FLT_MAX;
        int   ti0 = 0, ti1 = 0;
#pragma unroll 1
        for (int j = 0; j < 128; ++j) {
            const float v = y2s[j] - D2SCALE * epi[tid * 129 + j];
            const int idx = m0 + j;
            if (v < tv0)      { tv1 = tv0; ti1 = ti0; tv0 = v; ti0 = idx; }
            else if (v < tv1) { tv1 = v; ti1 = idx; }
        }
        Top2 t; t.v0 = tv0; t.v1 = tv1; t.i0 = ti0; t.i1 = ti1;
        g_top2[(size_t)(n0 + tid) * NCB + blockIdx.x] = t;
    }
}

// ---------------- K3: per-row candidate refinement in exact fp32 ----------------
__global__ void refine_kernel(const float* __restrict__ emb, const float* __restrict__ mb) {
    const int lane = threadIdx.x & 31;
    const int n = blockIdx.x * 8 + (threadIdx.x >> 5);

    float cv[8]; int ci[8];
    const Top2* tp = g_top2 + (size_t)n * NCB + lane * 4;
#pragma unroll
    for (int s = 0; s < 4; ++s) {
        Top2 t = tp[s];
        cv[2 * s]     = t.v0; ci[2 * s]     = t.i0;
        cv[2 * s + 1] = t.v1; ci[2 * s + 1] = t.i1;
    }
    int sel[8];
#pragma unroll 1
    for (int r = 0; r < 8; ++r) {       // top-8 of 256 candidates
        float bv = FLT_MAX; int bi = 0x7fffffff;
#pragma unroll
        for (int j = 0; j < 8; ++j)
            if (cv[j] < bv || (cv[j] == bv && ci[j] < bi)) { bv = cv[j]; bi = ci[j]; }
#pragma unroll
        for (int off = 16; off; off >>= 1) {
            float ov = __shfl_xor_sync(0xffffffffu, bv, off);
            int   oi = __shfl_xor_sync(0xffffffffu, bi, off);
            if (ov < bv || (ov == bv && oi < bi)) { bv = ov; bi = oi; }
        }
        sel[r] = bi;
#pragma unroll
        for (int j = 0; j < 8; ++j)
            if (ci[j] == bi) cv[j] = FLT_MAX;
    }
    float4 xl[12];
    const float4* x4 = reinterpret_cast<const float4*>(emb) + (size_t)n * (D_DIM / 4);
#pragma unroll
    for (int j = 0; j < 12; ++j) xl[j] = x4[lane + j * 32];
    const float xn = g_x2[n];
    float bestd = FLT_MAX; int besti = 0x7fffffff;
#pragma unroll 1
    for (int r = 0; r < 8; ++r) {
        const int m = sel[r];
        const float4* y4 = reinterpret_cast<const float4*>(mb) + (size_t)m * (D_DIM / 4);
        float s = 0.f;
#pragma unroll
        for (int j = 0; j < 12; ++j) {
            float4 bv = y4[lane + j * 32];
            s += xl[j].x * bv.x + xl[j].y * bv.y + xl[j].z * bv.z + xl[j].w * bv.w;
        }
#pragma unroll
        for (int off = 16; off; off >>= 1) s += __shfl_xor_sync(0xffffffffu, s, off);
        const float d2 = xn + g_y2[m] - 2.f * s;
        if (d2 < bestd || (d2 == bestd && m < besti)) { bestd = d2; besti = m; }
    }
    if (lane == 0) {
        g_pscore[n] = sqrtf(fmaxf(bestd, 0.f));
        g_ploc[n]   = besti;
    }
}

// ---------------- K4: per-batch argmax over patch scores ----------------
__global__ void argmax_kernel() {
    const int b = blockIdx.x;
    const int base = b * P_PT;
    const int tid = threadIdx.x;
    float bv = -FLT_MAX; int bi = 0x7fffffff;
    for (int i = tid; i < P_PT; i += 256) {
        const float v = g_pscore[base + i];
        if (v > bv || (v == bv && i < bi)) { bv = v; bi = i; }
    }
    __shared__ float sv[256]; __shared__ int si[256];
    sv[tid] = bv; si[tid] = bi;
    __syncthreads();
    for (int s = 128; s; s >>= 1) {
        if (tid < s) {
            if (sv[tid + s] > sv[tid] || (sv[tid + s] == sv[tid] && si[tid + s] < si[tid])) {
                sv[tid] = sv[tid + s]; si[tid] = si[tid + s];
            }
        }
        __syncthreads();
    }
    if (tid == 0) {
        const int n = base + si[0];
        g_bscore[b] = sv[0];
        g_bn[b]     = n;
        g_bnn[b]    = g_ploc[n];
    }
}

// ---------------- K5: fp32 distances nn_sample[b] <-> memory_bank ----------------
__global__ void stage2_kernel(const float* __restrict__ mb) {
    const int lane = threadIdx.x & 31;
    const int m = blockIdx.x * 8 + (threadIdx.x >> 5);
    const float4* y4 = reinterpret_cast<const float4*>(mb) + (size_t)m * (D_DIM / 4);
    float4 yl[12];
#pragma unroll
    for (int j = 0; j < 12; ++j) yl[j] = y4[lane + j * 32];
    const float ym = g_y2[m];
#pragma unroll 1
    for (int b = 0; b < B_SZ; ++b) {
        const int nn = g_bnn[b];
        const float4* x4 = reinterpret_cast<const float4*>(mb) + (size_t)nn * (D_DIM / 4);
        float s = 0.f;
#pragma unroll
        for (int j = 0; j < 12; ++j) {
            float4 a = x4[lane + j * 32];
            s += yl[j].x * a.x + yl[j].y * a.y + yl[j].z * a.z + yl[j].w * a.w;
        }
#pragma unroll
        for (int off = 16; off; off >>= 1) s += __shfl_xor_sync(0xffffffffu, s, off);
        if (lane == 0) g_d2b[(size_t)b * M_MB + m] = g_y2[nn] + ym - 2.f * s;
    }
}

// ---------------- K6: top-9 support, softmax re-weighting, output ----------------
__global__ void finalize_kernel(const float* __restrict__ emb, const float* __restrict__ mb,
                                float* __restrict__ out) {
    const int b = blockIdx.x;
    const int tid = threadIdx.x;
    __shared__ int sel[9];
    __shared__ float dist9[9];
    __shared__ float rv[256]; __shared__ int ri[256];
    const float* d2 = g_d2b + (size_t)b * M_MB;

    for (int j = 0; j < 9; ++j) {
        float bv = FLT_MAX; int bi = 0x7fffffff;
        for (int m = tid; m < M_MB; m += 256) {
            bool used = false;
            for (int q = 0; q < j; ++q) used |= (sel[q] == m);
            const float v = d2[m];
            if (!used && (v < bv || (v == bv && m < bi))) { bv = v; bi = m; }
        }
        rv[tid] = bv; ri[tid] = bi;
        __syncthreads();
        for (int s = 128; s; s >>= 1) {
            if (tid < s) {
                if (rv[tid + s] < rv[tid] || (rv[tid + s] == rv[tid] && ri[tid + s] < ri[tid])) {
                    rv[tid] = rv[tid + s]; ri[tid] = ri[tid + s];
                }
            }
            __syncthreads();
        }
        if (tid == 0) sel[j] = ri[0];
        __syncthreads();
    }

    const float* xp = emb + (size_t)g_bn[b] * D_DIM;
    for (int j = 0; j < 9; ++j) {
        const float* y = mb + (size_t)sel[j] * D_DIM;
        float s = 0.f;
        for (int k = tid; k < D_DIM; k += 256) { const float df = xp[k] - y[k]; s += df * df; }
        rv[tid] = s;
        __syncthreads();
        for (int st = 128; st; st >>= 1) {
            if (tid < st) rv[tid] += rv[tid + st];
            __syncthreads();
        }
        if (tid == 0) dist9[j] = sqrtf(fmaxf(rv[0], 0.f));
        __syncthreads();
    }
    if (tid == 0) {
        float mx = dist9[0];
        for (int j = 1; j < 9; ++j) mx = fmaxf(mx, dist9[j]);
        float sum = 0.f, e0 = 0.f;
        for (int j = 0; j < 9; ++j) {
            const float e = expf(dist9[j] - mx);
            if (j == 0) e0 = e;
            sum += e;
        }
        out[b] = (1.f - e0 / sum) * g_bscore[b];
    }
}

// ---------------- launch ----------------
extern "C" void kernel_launch(void* const* d_in, const int* in_sizes, int n_in,
                              void* d_out, int out_size) {
    const float* emb = (const float*)d_in[0];
    const float* mb  = (const float*)d_in[1];
    float* out = (float*)d_out;

    static bool s_attr_set = false;
    if (!s_attr_set) {
        cudaFuncSetAttribute(gemm_min_kernel, cudaFuncAttributeMaxDynamicSharedMemorySize,
                             GEMM_SMEM);
        s_attr_set = true;
    }

    prep_kernel<<<N_EMB, 128>>>(emb, 0);
    prep_kernel<<<M_MB, 128>>>(mb, 1);
    gemm_min_kernel<<<dim3(NCB, N_EMB / 256), 256, GEMM_SMEM>>>();
    refine_kernel<<<N_EMB / 8, 256>>>(emb, mb);
    argmax_kernel<<<B_SZ, 256>>>();
    stage2_kernel<<<M_MB / 8, 256>>>(mb);
    finalize_kernel<<<B_SZ, 256>>>(emb, mb, out);
}